// round 1
// baseline (speedup 1.0000x reference)
#include <cuda_runtime.h>

// Problem constants: B=4, S=2048, D=1024
#define BATCH 4
#define SEQ   2048
#define DMODEL 1024
#define BS_ROWS (BATCH*SEQ)            // 8192

#define BM 128
#define BN 128
#define BK 16

// Scratch (allocation-free rule: __device__ globals)
__device__ float g_Q[BS_ROWS * DMODEL];          // 32 MB
__device__ float g_K[BS_ROWS * DMODEL];          // 32 MB
__device__ float g_V[BS_ROWS * DMODEL];          // 32 MB
__device__ float g_O[BS_ROWS * DMODEL];          // 32 MB
__device__ float g_S[(size_t)BATCH * SEQ * SEQ]; // 64 MB

// ---- packed fp32x2 FMA (sm_103a; only reachable via PTX) ----
__device__ __forceinline__ unsigned long long splat2(float x) {
    unsigned long long r;
    unsigned u = __float_as_uint(x);
    asm("mov.b64 %0, {%1, %1};" : "=l"(r) : "r"(u));
    return r;
}
__device__ __forceinline__ void ffma2(unsigned long long& d,
                                      unsigned long long a,
                                      unsigned long long b) {
    asm("fma.rn.f32x2 %0, %1, %2, %0;" : "+l"(d) : "l"(a), "l"(b));
}

// C[M,N] = alpha * A @ op(B) (+ bias[n]), batched over blockIdx.z with strides.
// TB=true : B is [N,K] row-major (C = A B^T)
// TB=false: B is [K,N] row-major (C = A B)
template<bool TB, bool BIAS>
__global__ void __launch_bounds__(256)
sgemm(const float* __restrict__ A, const float* __restrict__ B,
      float* __restrict__ C, int M, int N, int K,
      long long sA, long long sB, long long sC,
      float alpha, const float* __restrict__ bias)
{
    __shared__ float As[2][BK][BM];
    __shared__ float Bs[2][BK][BN];

    A += (size_t)blockIdx.z * sA;
    B += (size_t)blockIdx.z * sB;
    C += (size_t)blockIdx.z * sC;

    const int m0 = blockIdx.y * BM;
    const int n0 = blockIdx.x * BN;
    const int tid = threadIdx.x;
    const int tx = tid & 15;   // column group (8 cols each)
    const int ty = tid >> 4;   // row group    (8 rows each)

    unsigned long long acc[8][4];
#pragma unroll
    for (int i = 0; i < 8; i++)
#pragma unroll
        for (int j = 0; j < 4; j++) acc[i][j] = 0ull;

    auto load_tile = [&](int buf, int kt) {
        // A tile: [BM x BK], transpose-store into As[k][m]
#pragma unroll
        for (int i = 0; i < 2; i++) {
            int f = tid + i * 256;
            int ml = f >> 2;
            int kk = (f & 3) << 2;
            float4 t = *(const float4*)(A + (size_t)(m0 + ml) * K + kt + kk);
            As[buf][kk + 0][ml] = t.x;
            As[buf][kk + 1][ml] = t.y;
            As[buf][kk + 2][ml] = t.z;
            As[buf][kk + 3][ml] = t.w;
        }
        if (TB) {
#pragma unroll
            for (int i = 0; i < 2; i++) {
                int f = tid + i * 256;
                int nl = f >> 2;
                int kk = (f & 3) << 2;
                float4 t = *(const float4*)(B + (size_t)(n0 + nl) * K + kt + kk);
                Bs[buf][kk + 0][nl] = t.x;
                Bs[buf][kk + 1][nl] = t.y;
                Bs[buf][kk + 2][nl] = t.z;
                Bs[buf][kk + 3][nl] = t.w;
            }
        } else {
#pragma unroll
            for (int i = 0; i < 2; i++) {
                int f = tid + i * 256;
                int kr = f >> 5;
                int nc = (f & 31) << 2;
                *(float4*)&Bs[buf][kr][nc] =
                    *(const float4*)(B + (size_t)(kt + kr) * N + n0 + nc);
            }
        }
    };

    load_tile(0, 0);
    __syncthreads();

    const int nt = K / BK;
    for (int t = 0; t < nt; ++t) {
        const int cur = t & 1;
        if (t + 1 < nt) load_tile(cur ^ 1, (t + 1) * BK);

#pragma unroll
        for (int k = 0; k < BK; ++k) {
            float a_frag[8];
            *(float4*)&a_frag[0] = *(float4*)&As[cur][k][ty * 8];
            *(float4*)&a_frag[4] = *(float4*)&As[cur][k][ty * 8 + 4];
            unsigned long long b_frag[4];
            const unsigned long long* bp =
                (const unsigned long long*)&Bs[cur][k][tx * 8];
#pragma unroll
            for (int j = 0; j < 4; j++) b_frag[j] = bp[j];
#pragma unroll
            for (int i = 0; i < 8; i++) {
                unsigned long long a2 = splat2(a_frag[i]);
#pragma unroll
                for (int j = 0; j < 4; j++) ffma2(acc[i][j], a2, b_frag[j]);
            }
        }
        __syncthreads();
    }

    // Epilogue
#pragma unroll
    for (int i = 0; i < 8; i++) {
        const int m = m0 + ty * 8 + i;
        float out[8];
#pragma unroll
        for (int j = 0; j < 4; j++) {
            out[2 * j]     = __uint_as_float((unsigned)(acc[i][j])) * alpha;
            out[2 * j + 1] = __uint_as_float((unsigned)(acc[i][j] >> 32)) * alpha;
        }
        if (BIAS) {
#pragma unroll
            for (int j = 0; j < 8; j++) out[j] += bias[n0 + tx * 8 + j];
        }
        *(float4*)(C + (size_t)m * N + n0 + tx * 8) =
            make_float4(out[0], out[1], out[2], out[3]);
        *(float4*)(C + (size_t)m * N + n0 + tx * 8 + 4) =
            make_float4(out[4], out[5], out[6], out[7]);
    }
}

// Row softmax over length-2048 rows, then add intensity. In-place on S.
__global__ void __launch_bounds__(256)
softmax_add(float* __restrict__ S, const float* __restrict__ inten)
{
    const size_t row = blockIdx.x;
    float* sr = S + row * SEQ;
    const float* ir = inten + row * SEQ;
    const int tid = threadIdx.x;

    float v[8];
    float mx = -3.4e38f;
#pragma unroll
    for (int i = 0; i < 8; i++) {
        v[i] = sr[tid + i * 256];
        mx = fmaxf(mx, v[i]);
    }
    __shared__ float red[8];
#pragma unroll
    for (int o = 16; o > 0; o >>= 1)
        mx = fmaxf(mx, __shfl_xor_sync(0xffffffffu, mx, o));
    if ((tid & 31) == 0) red[tid >> 5] = mx;
    __syncthreads();
    mx = red[0];
#pragma unroll
    for (int i = 1; i < 8; i++) mx = fmaxf(mx, red[i]);
    __syncthreads();  // everyone done reading red before reuse

    float sum = 0.f;
#pragma unroll
    for (int i = 0; i < 8; i++) {
        v[i] = expf(v[i] - mx);
        sum += v[i];
    }
#pragma unroll
    for (int o = 16; o > 0; o >>= 1)
        sum += __shfl_xor_sync(0xffffffffu, sum, o);
    if ((tid & 31) == 0) red[tid >> 5] = sum;
    __syncthreads();
    sum = 0.f;
#pragma unroll
    for (int i = 0; i < 8; i++) sum += red[i];
    const float inv = 1.f / sum;

#pragma unroll
    for (int i = 0; i < 8; i++)
        sr[tid + i * 256] = v[i] * inv + ir[tid + i * 256];
}

extern "C" void kernel_launch(void* const* d_in, const int* in_sizes, int n_in,
                              void* d_out, int out_size)
{
    const float* X  = (const float*)d_in[0];
    const float* I  = (const float*)d_in[1];
    const float* Wq = (const float*)d_in[2];
    const float* bq = (const float*)d_in[3];
    const float* Wk = (const float*)d_in[4];
    const float* bk = (const float*)d_in[5];
    const float* Wv = (const float*)d_in[6];
    const float* bv = (const float*)d_in[7];
    const float* Wo = (const float*)d_in[8];
    const float* bo = (const float*)d_in[9];
    float* out = (float*)d_out;

    float *Q, *Kp, *V, *O, *Sc;
    cudaGetSymbolAddress((void**)&Q,  g_Q);
    cudaGetSymbolAddress((void**)&Kp, g_K);
    cudaGetSymbolAddress((void**)&V,  g_V);
    cudaGetSymbolAddress((void**)&O,  g_O);
    cudaGetSymbolAddress((void**)&Sc, g_S);

    dim3 blk(256);

    // QKV projections: [8192,1024] = X[8192,1024] @ W^T + b
    dim3 gp(DMODEL / BN, BS_ROWS / BM, 1);
    sgemm<true, true><<<gp, blk>>>(X, Wq, Q, BS_ROWS, DMODEL, DMODEL, 0, 0, 0, 1.f, bq);
    sgemm<true, true><<<gp, blk>>>(X, Wk, Kp, BS_ROWS, DMODEL, DMODEL, 0, 0, 0, 1.f, bk);
    sgemm<true, true><<<gp, blk>>>(X, Wv, V, BS_ROWS, DMODEL, DMODEL, 0, 0, 0, 1.f, bv);

    // scores = (Q K^T) / 32, batched over 4
    dim3 gs(SEQ / BN, SEQ / BM, BATCH);
    sgemm<true, false><<<gs, blk>>>(Q, Kp, Sc, SEQ, SEQ, DMODEL,
                                    (long long)SEQ * DMODEL,
                                    (long long)SEQ * DMODEL,
                                    (long long)SEQ * SEQ,
                                    0.03125f, nullptr);

    // softmax rows + intensity (in-place on Sc)
    softmax_add<<<BATCH * SEQ, blk>>>(Sc, I);

    // O = attn @ V, batched
    dim3 ga(DMODEL / BN, SEQ / BM, BATCH);
    sgemm<false, false><<<ga, blk>>>(Sc, V, O, SEQ, DMODEL, SEQ,
                                     (long long)SEQ * SEQ,
                                     (long long)SEQ * DMODEL,
                                     (long long)SEQ * DMODEL,
                                     1.f, nullptr);

    // out = O @ Wo^T + bo
    sgemm<true, true><<<gp, blk>>>(O, Wo, out, BS_ROWS, DMODEL, DMODEL,
                                   0, 0, 0, 1.f, bo);
}

// round 3
// speedup vs baseline: 3.1195x; 3.1195x over previous
#include <cuda_runtime.h>
#include <cuda_bf16.h>
#include <cstdint>

#define BATCH 4
#define SEQ   2048
#define DMODEL 1024
#define BS_ROWS (BATCH*SEQ)   // 8192

#define BM 128
#define BN 128
#define BKE 64                 // bf16 K elems per stage (128B rows, SW128)
#define NTHREADS 256
#define STAGE_BYTES 65536      // Ahi 16K + Alo 16K + Bhi 16K + Blo 16K
#define SMEM_TOTAL (1024 + 2*STAGE_BYTES)

// ------------------------- scratch (device globals) -------------------------
__device__ __nv_bfloat16 g_Xhi[BS_ROWS*DMODEL], g_Xlo[BS_ROWS*DMODEL];
__device__ __nv_bfloat16 g_Whi[4*DMODEL*DMODEL], g_Wlo[4*DMODEL*DMODEL];
__device__ __nv_bfloat16 g_Qhi[BS_ROWS*DMODEL], g_Qlo[BS_ROWS*DMODEL];
__device__ __nv_bfloat16 g_Khi[BS_ROWS*DMODEL], g_Klo[BS_ROWS*DMODEL];
__device__ __nv_bfloat16 g_Vthi[(size_t)DMODEL*BS_ROWS], g_Vtlo[(size_t)DMODEL*BS_ROWS];
__device__ __nv_bfloat16 g_Ohi[BS_ROWS*DMODEL], g_Olo[BS_ROWS*DMODEL];
__device__ float g_S[(size_t)BATCH*SEQ*SEQ];
__device__ __nv_bfloat16 g_Phi[(size_t)BATCH*SEQ*SEQ], g_Plo[(size_t)BATCH*SEQ*SEQ];

// ------------------------- PTX helpers -------------------------
__device__ __forceinline__ uint32_t smem_u32(const void* p) {
    uint32_t a;
    asm("{ .reg .u64 t; cvta.to.shared.u64 t, %1; cvt.u32.u64 %0, t; }" : "=r"(a) : "l"(p));
    return a;
}
__device__ __forceinline__ uint32_t swz(uint32_t o) { return o ^ ((o >> 3) & 0x70); }

__device__ __forceinline__ void cp16(uint32_t s, const void* g) {
    asm volatile("cp.async.cg.shared.global [%0], [%1], 16;" :: "r"(s), "l"(g) : "memory");
}
__device__ __forceinline__ void cp_commit() { asm volatile("cp.async.commit_group;" ::: "memory"); }
__device__ __forceinline__ void cp_wait0()  { asm volatile("cp.async.wait_group 0;" ::: "memory"); }
__device__ __forceinline__ void cp_wait1()  { asm volatile("cp.async.wait_group 1;" ::: "memory"); }

__device__ __forceinline__ void ldsm4(uint32_t* r, uint32_t addr) {
    asm volatile("ldmatrix.sync.aligned.m8n8.x4.shared.b16 {%0,%1,%2,%3}, [%4];"
                 : "=r"(r[0]), "=r"(r[1]), "=r"(r[2]), "=r"(r[3]) : "r"(addr));
}
__device__ __forceinline__ void mma16816(float* d, const uint32_t* a, const uint32_t* b) {
    asm volatile(
        "mma.sync.aligned.m16n8k16.row.col.f32.bf16.bf16.f32 "
        "{%0,%1,%2,%3}, {%4,%5,%6,%7}, {%8,%9}, {%0,%1,%2,%3};"
        : "+f"(d[0]), "+f"(d[1]), "+f"(d[2]), "+f"(d[3])
        : "r"(a[0]), "r"(a[1]), "r"(a[2]), "r"(a[3]), "r"(b[0]), "r"(b[1]));
}

__device__ __forceinline__ void split1(float x, __nv_bfloat16& h, __nv_bfloat16& l) {
    h = __float2bfloat16(x);
    l = __float2bfloat16(x - __bfloat162float(h));
}
__device__ __forceinline__ uint32_t pack_bf2(__nv_bfloat16 a, __nv_bfloat16 b) {
    __nv_bfloat162 p; p.x = a; p.y = b;
    return *(uint32_t*)&p;
}

// ------------------------- GEMM: C = alpha * Ahi/lo @ (Bhi/lo)^T (+bias) -------------------------
// A: [M,K] K-major (lda), B: [N,K] K-major (ldb). BIAS_MODE: 0 none, 1 per-col, 2 per-row.
// SPLIT_OUT: write bf16 hi/lo instead of fp32 C. 3-term split MMA: hh + hl + lh.
template<int BIAS_MODE, bool SPLIT_OUT>
__global__ void __launch_bounds__(NTHREADS, 1)
gemm_hmma(const __nv_bfloat16* __restrict__ Ahi, const __nv_bfloat16* __restrict__ Alo,
          int lda, long long sA,
          const __nv_bfloat16* __restrict__ Bhi, const __nv_bfloat16* __restrict__ Blo,
          int ldb, long long sB,
          float* __restrict__ C, __nv_bfloat16* __restrict__ Chi, __nv_bfloat16* __restrict__ Clo,
          int ldc, long long sC,
          int Kdim, float alpha, const float* __restrict__ bias)
{
    extern __shared__ char smem_raw[];
    const uint32_t su = (smem_u32(smem_raw) + 1023u) & ~1023u;

    const int tid = threadIdx.x, lane = tid & 31, wid = tid >> 5;
    const int warp_m = wid >> 2;         // 0..1
    const int warp_n = wid & 3;          // 0..3
    const int m0 = blockIdx.y * BM, n0 = blockIdx.x * BN;
    const int z = blockIdx.z;

    Ahi += (size_t)z * sA;  Alo += (size_t)z * sA;
    Bhi += (size_t)z * sB;  Blo += (size_t)z * sB;
    if (SPLIT_OUT) { Chi += (size_t)z * sC; Clo += (size_t)z * sC; }
    else           { C   += (size_t)z * sC; }

    float acc[4][4][4];
#pragma unroll
    for (int i = 0; i < 4; i++)
#pragma unroll
        for (int j = 0; j < 4; j++)
#pragma unroll
            for (int r = 0; r < 4; r++) acc[i][j][r] = 0.f;

    auto load_stage = [&](int buf, int kt) {
        const uint32_t base = su + buf * STAGE_BYTES;
        const __nv_bfloat16* gAh = Ahi + (size_t)m0 * lda + kt;
        const __nv_bfloat16* gAl = Alo + (size_t)m0 * lda + kt;
        const __nv_bfloat16* gBh = Bhi + (size_t)n0 * ldb + kt;
        const __nv_bfloat16* gBl = Blo + (size_t)n0 * ldb + kt;
#pragma unroll
        for (int i = 0; i < 4; i++) {
            int u = tid + i * NTHREADS;          // 0..1023
            int r = u >> 3, e = (u & 7) * 8;     // row, elem offset (16B = 8 bf16)
            uint32_t so = swz((uint32_t)(r * 128 + e * 2));
            cp16(base +         so, gAh + (size_t)r * lda + e);
            cp16(base + 16384 + so, gAl + (size_t)r * lda + e);
            cp16(base + 32768 + so, gBh + (size_t)r * ldb + e);
            cp16(base + 49152 + so, gBl + (size_t)r * ldb + e);
        }
        cp_commit();
    };

    // ldmatrix lane address components
    const int arow = warp_m * 64 + (lane & 7) + ((lane >> 3) & 1) * 8;   // + mi*16
    const int achk = (lane >> 4) * 16;                                    // k byte
    const int brow = warp_n * 32 + (lane & 7) + ((lane >> 4) & 1) * 8;   // + nj2*16
    const int bchk = ((lane >> 3) & 1) * 16;

    auto compute = [&](int buf) {
        const uint32_t aAh = su + buf * STAGE_BYTES;
        const uint32_t aAl = aAh + 16384;
        const uint32_t aBh = aAh + 32768;
        const uint32_t aBl = aAh + 49152;
#pragma unroll
        for (int k16 = 0; k16 < 4; k16++) {
            const uint32_t kbA = (uint32_t)(k16 * 32 + achk);
            const uint32_t kbB = (uint32_t)(k16 * 32 + bchk);
            uint32_t ah[4][4], al[4][4];
#pragma unroll
            for (int mi = 0; mi < 4; mi++) {
                uint32_t off = swz((uint32_t)((arow + mi * 16) * 128) + kbA);
                ldsm4(ah[mi], aAh + off);
                ldsm4(al[mi], aAl + off);
            }
            uint32_t bh[4][2], bl[4][2];
#pragma unroll
            for (int nj2 = 0; nj2 < 2; nj2++) {
                uint32_t off = swz((uint32_t)((brow + nj2 * 16) * 128) + kbB);
                uint32_t t[4];
                ldsm4(t, aBh + off);
                bh[nj2*2][0] = t[0]; bh[nj2*2][1] = t[1];
                bh[nj2*2+1][0] = t[2]; bh[nj2*2+1][1] = t[3];
                ldsm4(t, aBl + off);
                bl[nj2*2][0] = t[0]; bl[nj2*2][1] = t[1];
                bl[nj2*2+1][0] = t[2]; bl[nj2*2+1][1] = t[3];
            }
#pragma unroll
            for (int mi = 0; mi < 4; mi++)
#pragma unroll
                for (int nj = 0; nj < 4; nj++) {
                    mma16816(acc[mi][nj], ah[mi], bh[nj]);
                    mma16816(acc[mi][nj], ah[mi], bl[nj]);
                    mma16816(acc[mi][nj], al[mi], bh[nj]);
                }
        }
    };

    const int NT = Kdim / BKE;
    load_stage(0, 0);
    for (int t = 0; t < NT; t++) {
        if (t + 1 < NT) { load_stage((t + 1) & 1, (t + 1) * BKE); cp_wait1(); }
        else            { cp_wait0(); }
        __syncthreads();
        compute(t & 1);
        __syncthreads();
    }

    // ---------------- epilogue: registers -> global ----------------
    const int gl = lane >> 2, q = lane & 3;
#pragma unroll
    for (int mi = 0; mi < 4; mi++) {
#pragma unroll
        for (int nj = 0; nj < 4; nj++) {
            const int n = n0 + warp_n * 32 + nj * 8 + q * 2;
            float bcol0 = 0.f, bcol1 = 0.f;
            if (BIAS_MODE == 1) { bcol0 = bias[n]; bcol1 = bias[n + 1]; }
#pragma unroll
            for (int h = 0; h < 2; h++) {
                const int m = m0 + warp_m * 64 + mi * 16 + gl + h * 8;
                float v0 = acc[mi][nj][2 * h + 0] * alpha;
                float v1 = acc[mi][nj][2 * h + 1] * alpha;
                if (BIAS_MODE == 1) { v0 += bcol0; v1 += bcol1; }
                if (BIAS_MODE == 2) { float bb = bias[m]; v0 += bb; v1 += bb; }
                const size_t gidx = (size_t)m * ldc + n;
                if (SPLIT_OUT) {
                    __nv_bfloat16 h0, h1, l0, l1;
                    split1(v0, h0, l0); split1(v1, h1, l1);
                    *(uint32_t*)(Chi + gidx) = pack_bf2(h0, h1);
                    *(uint32_t*)(Clo + gidx) = pack_bf2(l0, l1);
                } else {
                    *(float2*)(C + gidx) = make_float2(v0, v1);
                }
            }
        }
    }
}

// ------------------------- split fp32 -> bf16 hi/lo -------------------------
__global__ void __launch_bounds__(256)
split_f32(const float* __restrict__ x, __nv_bfloat16* __restrict__ hi,
          __nv_bfloat16* __restrict__ lo, int n4)
{
    int i = blockIdx.x * blockDim.x + threadIdx.x;
    if (i >= n4) return;
    float4 t = ((const float4*)x)[i];
    __nv_bfloat16 h0, h1, h2, h3, l0, l1, l2, l3;
    split1(t.x, h0, l0); split1(t.y, h1, l1);
    split1(t.z, h2, l2); split1(t.w, h3, l3);
    uint2 hv, lv;
    hv.x = pack_bf2(h0, h1); hv.y = pack_bf2(h2, h3);
    lv.x = pack_bf2(l0, l1); lv.y = pack_bf2(l2, l3);
    ((uint2*)hi)[i] = hv;
    ((uint2*)lo)[i] = lv;
}

// ------------------------- softmax + intensity, fused bf16 split out -------------------------
__global__ void __launch_bounds__(256)
softmax_split(const float* __restrict__ S, const float* __restrict__ inten,
              __nv_bfloat16* __restrict__ Phi, __nv_bfloat16* __restrict__ Plo)
{
    const size_t row = blockIdx.x;
    const float* sr = S + row * SEQ;
    const float* ir = inten + row * SEQ;
    const int tid = threadIdx.x;

    float v[8];
    float mx = -3.4e38f;
#pragma unroll
    for (int i = 0; i < 8; i++) {
        v[i] = sr[tid + i * 256];
        mx = fmaxf(mx, v[i]);
    }
    __shared__ float red[8];
#pragma unroll
    for (int o = 16; o > 0; o >>= 1)
        mx = fmaxf(mx, __shfl_xor_sync(0xffffffffu, mx, o));
    if ((tid & 31) == 0) red[tid >> 5] = mx;
    __syncthreads();
    mx = red[0];
#pragma unroll
    for (int i = 1; i < 8; i++) mx = fmaxf(mx, red[i]);
    __syncthreads();

    float sum = 0.f;
#pragma unroll
    for (int i = 0; i < 8; i++) {
        v[i] = expf(v[i] - mx);
        sum += v[i];
    }
#pragma unroll
    for (int o = 16; o > 0; o >>= 1)
        sum += __shfl_xor_sync(0xffffffffu, sum, o);
    if ((tid & 31) == 0) red[tid >> 5] = sum;
    __syncthreads();
    sum = 0.f;
#pragma unroll
    for (int i = 0; i < 8; i++) sum += red[i];
    const float inv = 1.f / sum;

    const size_t base = row * SEQ;
#pragma unroll
    for (int i = 0; i < 8; i++) {
        const int idx = tid + i * 256;
        float r = v[i] * inv + ir[idx];
        __nv_bfloat16 h, l;
        split1(r, h, l);
        Phi[base + idx] = h;
        Plo[base + idx] = l;
    }
}

// ------------------------- launch -------------------------
extern "C" void kernel_launch(void* const* d_in, const int* in_sizes, int n_in,
                              void* d_out, int out_size)
{
    const float* X  = (const float*)d_in[0];
    const float* I  = (const float*)d_in[1];
    const float* Wq = (const float*)d_in[2];
    const float* bq = (const float*)d_in[3];
    const float* Wk = (const float*)d_in[4];
    const float* bk = (const float*)d_in[5];
    const float* Wv = (const float*)d_in[6];
    const float* bv = (const float*)d_in[7];
    const float* Wo = (const float*)d_in[8];
    const float* bo = (const float*)d_in[9];
    float* out = (float*)d_out;

    __nv_bfloat16 *Xhi, *Xlo, *Whi, *Wlo, *Qhi, *Qlo, *Khi, *Klo;
    __nv_bfloat16 *Vthi, *Vtlo, *Ohi, *Olo, *Phi, *Plo;
    float* Sc;
    cudaGetSymbolAddress((void**)&Xhi,  g_Xhi);
    cudaGetSymbolAddress((void**)&Xlo,  g_Xlo);
    cudaGetSymbolAddress((void**)&Whi,  g_Whi);
    cudaGetSymbolAddress((void**)&Wlo,  g_Wlo);
    cudaGetSymbolAddress((void**)&Qhi,  g_Qhi);
    cudaGetSymbolAddress((void**)&Qlo,  g_Qlo);
    cudaGetSymbolAddress((void**)&Khi,  g_Khi);
    cudaGetSymbolAddress((void**)&Klo,  g_Klo);
    cudaGetSymbolAddress((void**)&Vthi, g_Vthi);
    cudaGetSymbolAddress((void**)&Vtlo, g_Vtlo);
    cudaGetSymbolAddress((void**)&Ohi,  g_Ohi);
    cudaGetSymbolAddress((void**)&Olo,  g_Olo);
    cudaGetSymbolAddress((void**)&Phi,  g_Phi);
    cudaGetSymbolAddress((void**)&Plo,  g_Plo);
    cudaGetSymbolAddress((void**)&Sc,   g_S);

    cudaFuncSetAttribute(gemm_hmma<1, true>,  cudaFuncAttributeMaxDynamicSharedMemorySize, SMEM_TOTAL);
    cudaFuncSetAttribute(gemm_hmma<2, true>,  cudaFuncAttributeMaxDynamicSharedMemorySize, SMEM_TOTAL);
    cudaFuncSetAttribute(gemm_hmma<0, false>, cudaFuncAttributeMaxDynamicSharedMemorySize, SMEM_TOTAL);
    cudaFuncSetAttribute(gemm_hmma<0, true>,  cudaFuncAttributeMaxDynamicSharedMemorySize, SMEM_TOTAL);
    cudaFuncSetAttribute(gemm_hmma<1, false>, cudaFuncAttributeMaxDynamicSharedMemorySize, SMEM_TOTAL);

    const int WSZ = DMODEL * DMODEL;

    // split inputs to bf16 hi/lo
    split_f32<<<(BS_ROWS * DMODEL / 4 + 255) / 256, 256>>>(X, Xhi, Xlo, BS_ROWS * DMODEL / 4);
    split_f32<<<(WSZ / 4 + 255) / 256, 256>>>(Wq, Whi + 0 * WSZ, Wlo + 0 * WSZ, WSZ / 4);
    split_f32<<<(WSZ / 4 + 255) / 256, 256>>>(Wk, Whi + 1 * WSZ, Wlo + 1 * WSZ, WSZ / 4);
    split_f32<<<(WSZ / 4 + 255) / 256, 256>>>(Wv, Whi + 2 * WSZ, Wlo + 2 * WSZ, WSZ / 4);
    split_f32<<<(WSZ / 4 + 255) / 256, 256>>>(Wo, Whi + 3 * WSZ, Wlo + 3 * WSZ, WSZ / 4);

    dim3 blk(NTHREADS);

    // Q = X @ Wq^T + bq   -> split
    dim3 gP(DMODEL / BN, BS_ROWS / BM, 1);  // (8, 64)
    gemm_hmma<1, true><<<gP, blk, SMEM_TOTAL>>>(
        Xhi, Xlo, DMODEL, 0, Whi + 0 * WSZ, Wlo + 0 * WSZ, DMODEL, 0,
        nullptr, Qhi, Qlo, DMODEL, 0, DMODEL, 1.f, bq);
    // K = X @ Wk^T + bk   -> split
    gemm_hmma<1, true><<<gP, blk, SMEM_TOTAL>>>(
        Xhi, Xlo, DMODEL, 0, Whi + 1 * WSZ, Wlo + 1 * WSZ, DMODEL, 0,
        nullptr, Khi, Klo, DMODEL, 0, DMODEL, 1.f, bk);
    // V^T = Wv @ X^T + bv(row)  -> split, Vt[d, b*S+s], ld = 8192
    dim3 gV(BS_ROWS / BN, DMODEL / BM, 1);  // (64, 8)
    gemm_hmma<2, true><<<gV, blk, SMEM_TOTAL>>>(
        Whi + 2 * WSZ, Wlo + 2 * WSZ, DMODEL, 0, Xhi, Xlo, DMODEL, 0,
        nullptr, Vthi, Vtlo, BS_ROWS, 0, DMODEL, 1.f, bv);
    // scores = (Q K^T)/32  -> fp32, batched
    dim3 gS(SEQ / BN, SEQ / BM, BATCH);     // (16, 16, 4)
    gemm_hmma<0, false><<<gS, blk, SMEM_TOTAL>>>(
        Qhi, Qlo, DMODEL, (long long)SEQ * DMODEL,
        Khi, Klo, DMODEL, (long long)SEQ * DMODEL,
        Sc, nullptr, nullptr, SEQ, (long long)SEQ * SEQ,
        DMODEL, 0.03125f, nullptr);
    // attn = softmax(scores) + intensity -> split
    softmax_split<<<BATCH * SEQ, 256>>>(Sc, I, Phi, Plo);
    // O = attn @ (Vt)^T  -> split, batched (B slice = column offset b*S within Vt rows)
    dim3 gO(DMODEL / BN, SEQ / BM, BATCH);  // (8, 16, 4)
    gemm_hmma<0, true><<<gO, blk, SMEM_TOTAL>>>(
        Phi, Plo, SEQ, (long long)SEQ * SEQ,
        Vthi, Vtlo, BS_ROWS, (long long)SEQ,
        nullptr, Ohi, Olo, DMODEL, (long long)SEQ * DMODEL,
        SEQ, 1.f, nullptr);
    // out = O @ Wo^T + bo  -> fp32
    gemm_hmma<1, false><<<gP, blk, SMEM_TOTAL>>>(
        Ohi, Olo, DMODEL, 0, Whi + 3 * WSZ, Wlo + 3 * WSZ, DMODEL, 0,
        out, nullptr, nullptr, DMODEL, 0, DMODEL, 1.f, bo);
}

// round 4
// speedup vs baseline: 3.1892x; 1.0223x over previous
#include <cuda_runtime.h>
#include <cuda_bf16.h>
#include <cstdint>

#define BATCH 4
#define SEQ   2048
#define DMODEL 1024
#define BS_ROWS (BATCH*SEQ)   // 8192

#define BM 128
#define BN 128
#define BKE 64                 // bf16 K elems per stage (128B rows, SW128)
#define NTHREADS 256
#define NSTAGE 3
#define STAGE_BYTES 65536      // Ahi 16K + Alo 16K + Bhi 16K + Blo 16K
#define SMEM_TOTAL (1024 + NSTAGE*STAGE_BYTES)

// ------------------------- scratch (device globals) -------------------------
__device__ __nv_bfloat16 g_Xhi[BS_ROWS*DMODEL], g_Xlo[BS_ROWS*DMODEL];
__device__ __nv_bfloat16 g_Whi[4*DMODEL*DMODEL], g_Wlo[4*DMODEL*DMODEL];
__device__ __nv_bfloat16 g_Qhi[BS_ROWS*DMODEL], g_Qlo[BS_ROWS*DMODEL];
__device__ __nv_bfloat16 g_Khi[BS_ROWS*DMODEL], g_Klo[BS_ROWS*DMODEL];
__device__ __nv_bfloat16 g_Vthi[(size_t)DMODEL*BS_ROWS], g_Vtlo[(size_t)DMODEL*BS_ROWS];
__device__ __nv_bfloat16 g_Ohi[BS_ROWS*DMODEL], g_Olo[BS_ROWS*DMODEL];
__device__ float g_S[(size_t)BATCH*SEQ*SEQ];
__device__ __nv_bfloat16 g_Phi[(size_t)BATCH*SEQ*SEQ], g_Plo[(size_t)BATCH*SEQ*SEQ];

// ------------------------- PTX helpers -------------------------
__device__ __forceinline__ uint32_t smem_u32(const void* p) {
    uint32_t a;
    asm("{ .reg .u64 t; cvta.to.shared.u64 t, %1; cvt.u32.u64 %0, t; }" : "=r"(a) : "l"(p));
    return a;
}
__device__ __forceinline__ uint32_t swz(uint32_t o) { return o ^ ((o >> 3) & 0x70); }

__device__ __forceinline__ void cp16(uint32_t s, const void* g) {
    asm volatile("cp.async.cg.shared.global [%0], [%1], 16;" :: "r"(s), "l"(g) : "memory");
}
__device__ __forceinline__ void cp_commit() { asm volatile("cp.async.commit_group;" ::: "memory"); }
__device__ __forceinline__ void cp_wait0()  { asm volatile("cp.async.wait_group 0;" ::: "memory"); }
__device__ __forceinline__ void cp_wait1()  { asm volatile("cp.async.wait_group 1;" ::: "memory"); }

__device__ __forceinline__ void ldsm4(uint32_t* r, uint32_t addr) {
    asm volatile("ldmatrix.sync.aligned.m8n8.x4.shared.b16 {%0,%1,%2,%3}, [%4];"
                 : "=r"(r[0]), "=r"(r[1]), "=r"(r[2]), "=r"(r[3]) : "r"(addr));
}
__device__ __forceinline__ void mma16816(float* d, const uint32_t* a, const uint32_t* b) {
    asm volatile(
        "mma.sync.aligned.m16n8k16.row.col.f32.bf16.bf16.f32 "
        "{%0,%1,%2,%3}, {%4,%5,%6,%7}, {%8,%9}, {%0,%1,%2,%3};"
        : "+f"(d[0]), "+f"(d[1]), "+f"(d[2]), "+f"(d[3])
        : "r"(a[0]), "r"(a[1]), "r"(a[2]), "r"(a[3]), "r"(b[0]), "r"(b[1]));
}

__device__ __forceinline__ void split1(float x, __nv_bfloat16& h, __nv_bfloat16& l) {
    h = __float2bfloat16(x);
    l = __float2bfloat16(x - __bfloat162float(h));
}
__device__ __forceinline__ uint32_t pack_bf2(__nv_bfloat16 a, __nv_bfloat16 b) {
    __nv_bfloat162 p; p.x = a; p.y = b;
    return *(uint32_t*)&p;
}

// ------------------------- GEMM: C = alpha * Ahi/lo @ (Bhi/lo)^T (+bias) -------------------------
// A: [M,K] K-major (lda), B: [N,K] K-major (ldb). BIAS_MODE: 0 none, 1 per-col, 2 per-row.
// SPLIT_OUT: write bf16 hi/lo instead of fp32 C. 3-term split MMA: hh + hl + lh.
template<int BIAS_MODE, bool SPLIT_OUT>
__global__ void __launch_bounds__(NTHREADS, 1)
gemm_hmma(const __nv_bfloat16* __restrict__ Ahi, const __nv_bfloat16* __restrict__ Alo,
          int lda, long long sA,
          const __nv_bfloat16* __restrict__ Bhi, const __nv_bfloat16* __restrict__ Blo,
          int ldb, long long sB,
          float* __restrict__ C, __nv_bfloat16* __restrict__ Chi, __nv_bfloat16* __restrict__ Clo,
          int ldc, long long sC,
          int Kdim, float alpha, const float* __restrict__ bias)
{
    extern __shared__ char smem_raw[];
    const uint32_t su = (smem_u32(smem_raw) + 1023u) & ~1023u;

    const int tid = threadIdx.x, lane = tid & 31, wid = tid >> 5;
    const int warp_m = wid >> 2;         // 0..1
    const int warp_n = wid & 3;          // 0..3
    const int m0 = blockIdx.y * BM, n0 = blockIdx.x * BN;
    const int z = blockIdx.z;

    Ahi += (size_t)z * sA;  Alo += (size_t)z * sA;
    Bhi += (size_t)z * sB;  Blo += (size_t)z * sB;
    if (SPLIT_OUT) { Chi += (size_t)z * sC; Clo += (size_t)z * sC; }
    else           { C   += (size_t)z * sC; }

    float acc[4][4][4];
#pragma unroll
    for (int i = 0; i < 4; i++)
#pragma unroll
        for (int j = 0; j < 4; j++)
#pragma unroll
            for (int r = 0; r < 4; r++) acc[i][j][r] = 0.f;

    auto load_stage = [&](int buf, int kt) {
        const uint32_t base = su + buf * STAGE_BYTES;
        const __nv_bfloat16* gAh = Ahi + (size_t)m0 * lda + kt;
        const __nv_bfloat16* gAl = Alo + (size_t)m0 * lda + kt;
        const __nv_bfloat16* gBh = Bhi + (size_t)n0 * ldb + kt;
        const __nv_bfloat16* gBl = Blo + (size_t)n0 * ldb + kt;
#pragma unroll
        for (int i = 0; i < 4; i++) {
            int u = tid + i * NTHREADS;          // 0..1023
            int r = u >> 3, e = (u & 7) * 8;     // row, elem offset (16B = 8 bf16)
            uint32_t so = swz((uint32_t)(r * 128 + e * 2));
            cp16(base +         so, gAh + (size_t)r * lda + e);
            cp16(base + 16384 + so, gAl + (size_t)r * lda + e);
            cp16(base + 32768 + so, gBh + (size_t)r * ldb + e);
            cp16(base + 49152 + so, gBl + (size_t)r * ldb + e);
        }
        cp_commit();
    };

    // ldmatrix lane address components
    const int arow = warp_m * 64 + (lane & 7) + ((lane >> 3) & 1) * 8;   // + mi*16
    const int achk = (lane >> 4) * 16;                                    // k byte
    const int brow = warp_n * 32 + (lane & 7) + ((lane >> 4) & 1) * 8;   // + nj2*16
    const int bchk = ((lane >> 3) & 1) * 16;

    auto compute = [&](int buf) {
        const uint32_t aAh = su + buf * STAGE_BYTES;
        const uint32_t aAl = aAh + 16384;
        const uint32_t aBh = aAh + 32768;
        const uint32_t aBl = aAh + 49152;
#pragma unroll
        for (int k16 = 0; k16 < 4; k16++) {
            const uint32_t kbA = (uint32_t)(k16 * 32 + achk);
            const uint32_t kbB = (uint32_t)(k16 * 32 + bchk);
            uint32_t ah[4][4], al[4][4];
#pragma unroll
            for (int mi = 0; mi < 4; mi++) {
                uint32_t off = swz((uint32_t)((arow + mi * 16) * 128) + kbA);
                ldsm4(ah[mi], aAh + off);
                ldsm4(al[mi], aAl + off);
            }
            uint32_t bh[4][2], bl[4][2];
#pragma unroll
            for (int nj2 = 0; nj2 < 2; nj2++) {
                uint32_t off = swz((uint32_t)((brow + nj2 * 16) * 128) + kbB);
                uint32_t t[4];
                ldsm4(t, aBh + off);
                bh[nj2*2][0] = t[0]; bh[nj2*2][1] = t[1];
                bh[nj2*2+1][0] = t[2]; bh[nj2*2+1][1] = t[3];
                ldsm4(t, aBl + off);
                bl[nj2*2][0] = t[0]; bl[nj2*2][1] = t[1];
                bl[nj2*2+1][0] = t[2]; bl[nj2*2+1][1] = t[3];
            }
            // term-major: 16 independent accumulators between same-acc reuses
#pragma unroll
            for (int mi = 0; mi < 4; mi++)
#pragma unroll
                for (int nj = 0; nj < 4; nj++)
                    mma16816(acc[mi][nj], ah[mi], bh[nj]);
#pragma unroll
            for (int mi = 0; mi < 4; mi++)
#pragma unroll
                for (int nj = 0; nj < 4; nj++)
                    mma16816(acc[mi][nj], ah[mi], bl[nj]);
#pragma unroll
            for (int mi = 0; mi < 4; mi++)
#pragma unroll
                for (int nj = 0; nj < 4; nj++)
                    mma16816(acc[mi][nj], al[mi], bh[nj]);
        }
    };

    const int NT = Kdim / BKE;
    load_stage(0, 0);
    if (NT > 1) load_stage(1, BKE);
    for (int t = 0; t < NT; t++) {
        if (t + 1 < NT) cp_wait1(); else cp_wait0();
        __syncthreads();   // group t visible to all; all done reading buf (t+2)%3's previous life
        if (t + 2 < NT) load_stage((t + 2) % NSTAGE, (t + 2) * BKE);
        compute(t % NSTAGE);
    }

    // ---------------- epilogue: registers -> global ----------------
    const int gl = lane >> 2, q = lane & 3;
#pragma unroll
    for (int mi = 0; mi < 4; mi++) {
#pragma unroll
        for (int nj = 0; nj < 4; nj++) {
            const int n = n0 + warp_n * 32 + nj * 8 + q * 2;
            float bcol0 = 0.f, bcol1 = 0.f;
            if (BIAS_MODE == 1) { bcol0 = bias[n]; bcol1 = bias[n + 1]; }
#pragma unroll
            for (int h = 0; h < 2; h++) {
                const int m = m0 + warp_m * 64 + mi * 16 + gl + h * 8;
                float v0 = acc[mi][nj][2 * h + 0] * alpha;
                float v1 = acc[mi][nj][2 * h + 1] * alpha;
                if (BIAS_MODE == 1) { v0 += bcol0; v1 += bcol1; }
                if (BIAS_MODE == 2) { float bb = bias[m]; v0 += bb; v1 += bb; }
                const size_t gidx = (size_t)m * ldc + n;
                if (SPLIT_OUT) {
                    __nv_bfloat16 h0, h1, l0, l1;
                    split1(v0, h0, l0); split1(v1, h1, l1);
                    *(uint32_t*)(Chi + gidx) = pack_bf2(h0, h1);
                    *(uint32_t*)(Clo + gidx) = pack_bf2(l0, l1);
                } else {
                    *(float2*)(C + gidx) = make_float2(v0, v1);
                }
            }
        }
    }
}

// ------------------------- split fp32 -> bf16 hi/lo -------------------------
__global__ void __launch_bounds__(256)
split_f32(const float* __restrict__ x, __nv_bfloat16* __restrict__ hi,
          __nv_bfloat16* __restrict__ lo, int n4)
{
    int i = blockIdx.x * blockDim.x + threadIdx.x;
    if (i >= n4) return;
    float4 t = ((const float4*)x)[i];
    __nv_bfloat16 h0, h1, h2, h3, l0, l1, l2, l3;
    split1(t.x, h0, l0); split1(t.y, h1, l1);
    split1(t.z, h2, l2); split1(t.w, h3, l3);
    uint2 hv, lv;
    hv.x = pack_bf2(h0, h1); hv.y = pack_bf2(h2, h3);
    lv.x = pack_bf2(l0, l1); lv.y = pack_bf2(l2, l3);
    ((uint2*)hi)[i] = hv;
    ((uint2*)lo)[i] = lv;
}

// ------------------------- softmax + intensity, fused bf16 split out -------------------------
__global__ void __launch_bounds__(256)
softmax_split(const float* __restrict__ S, const float* __restrict__ inten,
              __nv_bfloat16* __restrict__ Phi, __nv_bfloat16* __restrict__ Plo)
{
    const size_t row = blockIdx.x;
    const float* sr = S + row * SEQ;
    const float* ir = inten + row * SEQ;
    const int tid = threadIdx.x;

    float v[8];
    float mx = -3.4e38f;
#pragma unroll
    for (int i = 0; i < 8; i++) {
        v[i] = sr[tid + i * 256];
        mx = fmaxf(mx, v[i]);
    }
    __shared__ float red[8];
#pragma unroll
    for (int o = 16; o > 0; o >>= 1)
        mx = fmaxf(mx, __shfl_xor_sync(0xffffffffu, mx, o));
    if ((tid & 31) == 0) red[tid >> 5] = mx;
    __syncthreads();
    mx = red[0];
#pragma unroll
    for (int i = 1; i < 8; i++) mx = fmaxf(mx, red[i]);
    __syncthreads();

    float sum = 0.f;
#pragma unroll
    for (int i = 0; i < 8; i++) {
        v[i] = expf(v[i] - mx);
        sum += v[i];
    }
#pragma unroll
    for (int o = 16; o > 0; o >>= 1)
        sum += __shfl_xor_sync(0xffffffffu, sum, o);
    if ((tid & 31) == 0) red[tid >> 5] = sum;
    __syncthreads();
    sum = 0.f;
#pragma unroll
    for (int i = 0; i < 8; i++) sum += red[i];
    const float inv = 1.f / sum;

    const size_t base = row * SEQ;
#pragma unroll
    for (int i = 0; i < 8; i++) {
        const int idx = tid + i * 256;
        float r = v[i] * inv + ir[idx];
        __nv_bfloat16 h, l;
        split1(r, h, l);
        Phi[base + idx] = h;
        Plo[base + idx] = l;
    }
}

// ------------------------- launch -------------------------
extern "C" void kernel_launch(void* const* d_in, const int* in_sizes, int n_in,
                              void* d_out, int out_size)
{
    const float* X  = (const float*)d_in[0];
    const float* I  = (const float*)d_in[1];
    const float* Wq = (const float*)d_in[2];
    const float* bq = (const float*)d_in[3];
    const float* Wk = (const float*)d_in[4];
    const float* bk = (const float*)d_in[5];
    const float* Wv = (const float*)d_in[6];
    const float* bv = (const float*)d_in[7];
    const float* Wo = (const float*)d_in[8];
    const float* bo = (const float*)d_in[9];
    float* out = (float*)d_out;

    __nv_bfloat16 *Xhi, *Xlo, *Whi, *Wlo, *Qhi, *Qlo, *Khi, *Klo;
    __nv_bfloat16 *Vthi, *Vtlo, *Ohi, *Olo, *Phi, *Plo;
    float* Sc;
    cudaGetSymbolAddress((void**)&Xhi,  g_Xhi);
    cudaGetSymbolAddress((void**)&Xlo,  g_Xlo);
    cudaGetSymbolAddress((void**)&Whi,  g_Whi);
    cudaGetSymbolAddress((void**)&Wlo,  g_Wlo);
    cudaGetSymbolAddress((void**)&Qhi,  g_Qhi);
    cudaGetSymbolAddress((void**)&Qlo,  g_Qlo);
    cudaGetSymbolAddress((void**)&Khi,  g_Khi);
    cudaGetSymbolAddress((void**)&Klo,  g_Klo);
    cudaGetSymbolAddress((void**)&Vthi, g_Vthi);
    cudaGetSymbolAddress((void**)&Vtlo, g_Vtlo);
    cudaGetSymbolAddress((void**)&Ohi,  g_Ohi);
    cudaGetSymbolAddress((void**)&Olo,  g_Olo);
    cudaGetSymbolAddress((void**)&Phi,  g_Phi);
    cudaGetSymbolAddress((void**)&Plo,  g_Plo);
    cudaGetSymbolAddress((void**)&Sc,   g_S);

    cudaFuncSetAttribute(gemm_hmma<1, true>,  cudaFuncAttributeMaxDynamicSharedMemorySize, SMEM_TOTAL);
    cudaFuncSetAttribute(gemm_hmma<2, true>,  cudaFuncAttributeMaxDynamicSharedMemorySize, SMEM_TOTAL);
    cudaFuncSetAttribute(gemm_hmma<0, false>, cudaFuncAttributeMaxDynamicSharedMemorySize, SMEM_TOTAL);
    cudaFuncSetAttribute(gemm_hmma<0, true>,  cudaFuncAttributeMaxDynamicSharedMemorySize, SMEM_TOTAL);
    cudaFuncSetAttribute(gemm_hmma<1, false>, cudaFuncAttributeMaxDynamicSharedMemorySize, SMEM_TOTAL);

    const int WSZ = DMODEL * DMODEL;

    // split inputs to bf16 hi/lo
    split_f32<<<(BS_ROWS * DMODEL / 4 + 255) / 256, 256>>>(X, Xhi, Xlo, BS_ROWS * DMODEL / 4);
    split_f32<<<(WSZ / 4 + 255) / 256, 256>>>(Wq, Whi + 0 * WSZ, Wlo + 0 * WSZ, WSZ / 4);
    split_f32<<<(WSZ / 4 + 255) / 256, 256>>>(Wk, Whi + 1 * WSZ, Wlo + 1 * WSZ, WSZ / 4);
    split_f32<<<(WSZ / 4 + 255) / 256, 256>>>(Wv, Whi + 2 * WSZ, Wlo + 2 * WSZ, WSZ / 4);
    split_f32<<<(WSZ / 4 + 255) / 256, 256>>>(Wo, Whi + 3 * WSZ, Wlo + 3 * WSZ, WSZ / 4);

    dim3 blk(NTHREADS);

    // Q = X @ Wq^T + bq   -> split
    dim3 gP(DMODEL / BN, BS_ROWS / BM, 1);  // (8, 64)
    gemm_hmma<1, true><<<gP, blk, SMEM_TOTAL>>>(
        Xhi, Xlo, DMODEL, 0, Whi + 0 * WSZ, Wlo + 0 * WSZ, DMODEL, 0,
        nullptr, Qhi, Qlo, DMODEL, 0, DMODEL, 1.f, bq);
    // K = X @ Wk^T + bk   -> split
    gemm_hmma<1, true><<<gP, blk, SMEM_TOTAL>>>(
        Xhi, Xlo, DMODEL, 0, Whi + 1 * WSZ, Wlo + 1 * WSZ, DMODEL, 0,
        nullptr, Khi, Klo, DMODEL, 0, DMODEL, 1.f, bk);
    // V^T = Wv @ X^T + bv(row)  -> split, Vt[d, b*S+s], ld = 8192
    dim3 gV(BS_ROWS / BN, DMODEL / BM, 1);  // (64, 8)
    gemm_hmma<2, true><<<gV, blk, SMEM_TOTAL>>>(
        Whi + 2 * WSZ, Wlo + 2 * WSZ, DMODEL, 0, Xhi, Xlo, DMODEL, 0,
        nullptr, Vthi, Vtlo, BS_ROWS, 0, DMODEL, 1.f, bv);
    // scores = (Q K^T)/32  -> fp32, batched
    dim3 gS(SEQ / BN, SEQ / BM, BATCH);     // (16, 16, 4)
    gemm_hmma<0, false><<<gS, blk, SMEM_TOTAL>>>(
        Qhi, Qlo, DMODEL, (long long)SEQ * DMODEL,
        Khi, Klo, DMODEL, (long long)SEQ * DMODEL,
        Sc, nullptr, nullptr, SEQ, (long long)SEQ * SEQ,
        DMODEL, 0.03125f, nullptr);
    // attn = softmax(scores) + intensity -> split
    softmax_split<<<BATCH * SEQ, 256>>>(Sc, I, Phi, Plo);
    // O = attn @ (Vt)^T  -> split, batched (B slice = column offset b*S within Vt rows)
    dim3 gO(DMODEL / BN, SEQ / BM, BATCH);  // (8, 16, 4)
    gemm_hmma<0, true><<<gO, blk, SMEM_TOTAL>>>(
        Phi, Plo, SEQ, (long long)SEQ * SEQ,
        Vthi, Vtlo, BS_ROWS, (long long)SEQ,
        nullptr, Ohi, Olo, DMODEL, (long long)SEQ * DMODEL,
        SEQ, 1.f, nullptr);
    // out = O @ Wo^T + bo  -> fp32
    gemm_hmma<1, false><<<gP, blk, SMEM_TOTAL>>>(
        Ohi, Olo, DMODEL, 0, Whi + 3 * WSZ, Wlo + 3 * WSZ, DMODEL, 0,
        out, nullptr, nullptr, DMODEL, 0, DMODEL, 1.f, bo);
}

// round 5
// speedup vs baseline: 3.1978x; 1.0027x over previous
#include <cuda_runtime.h>
#include <cuda_bf16.h>
#include <cstdint>

#define BATCH 4
#define SEQ   2048
#define DMODEL 1024
#define BS_ROWS (BATCH*SEQ)   // 8192

#define BM 256
#define BN 128
#define BKE 64                 // bf16 K elems per stage (128B rows, SW128)
#define NTHREADS 256
#define NSTAGE 2
#define STAGE_BYTES 98304      // Ahi 32K + Alo 32K + Bhi 16K + Blo 16K
#define SMEM_TOTAL (1024 + NSTAGE*STAGE_BYTES)

// ------------------------- scratch (device globals) -------------------------
__device__ __nv_bfloat16 g_Xhi[BS_ROWS*DMODEL], g_Xlo[BS_ROWS*DMODEL];
__device__ __nv_bfloat16 g_Whi[4*DMODEL*DMODEL], g_Wlo[4*DMODEL*DMODEL];
__device__ __nv_bfloat16 g_Qhi[BS_ROWS*DMODEL], g_Qlo[BS_ROWS*DMODEL];
__device__ __nv_bfloat16 g_Khi[BS_ROWS*DMODEL], g_Klo[BS_ROWS*DMODEL];
__device__ __nv_bfloat16 g_Vthi[(size_t)DMODEL*BS_ROWS], g_Vtlo[(size_t)DMODEL*BS_ROWS];
__device__ __nv_bfloat16 g_Ohi[BS_ROWS*DMODEL], g_Olo[BS_ROWS*DMODEL];
__device__ float g_S[(size_t)BATCH*SEQ*SEQ];
__device__ __nv_bfloat16 g_Phi[(size_t)BATCH*SEQ*SEQ], g_Plo[(size_t)BATCH*SEQ*SEQ];

// ------------------------- PTX helpers -------------------------
__device__ __forceinline__ uint32_t smem_u32(const void* p) {
    uint32_t a;
    asm("{ .reg .u64 t; cvta.to.shared.u64 t, %1; cvt.u32.u64 %0, t; }" : "=r"(a) : "l"(p));
    return a;
}
__device__ __forceinline__ uint32_t swz(uint32_t o) { return o ^ ((o >> 3) & 0x70); }

__device__ __forceinline__ void cp16(uint32_t s, const void* g) {
    asm volatile("cp.async.cg.shared.global [%0], [%1], 16;" :: "r"(s), "l"(g) : "memory");
}
__device__ __forceinline__ void cp_commit() { asm volatile("cp.async.commit_group;" ::: "memory"); }
__device__ __forceinline__ void cp_wait0()  { asm volatile("cp.async.wait_group 0;" ::: "memory"); }
__device__ __forceinline__ void cp_wait1()  { asm volatile("cp.async.wait_group 1;" ::: "memory"); }

__device__ __forceinline__ void ldsm4(uint32_t* r, uint32_t addr) {
    asm volatile("ldmatrix.sync.aligned.m8n8.x4.shared.b16 {%0,%1,%2,%3}, [%4];"
                 : "=r"(r[0]), "=r"(r[1]), "=r"(r[2]), "=r"(r[3]) : "r"(addr));
}
__device__ __forceinline__ void mma16816(float* d, const uint32_t* a, const uint32_t* b) {
    asm volatile(
        "mma.sync.aligned.m16n8k16.row.col.f32.bf16.bf16.f32 "
        "{%0,%1,%2,%3}, {%4,%5,%6,%7}, {%8,%9}, {%0,%1,%2,%3};"
        : "+f"(d[0]), "+f"(d[1]), "+f"(d[2]), "+f"(d[3])
        : "r"(a[0]), "r"(a[1]), "r"(a[2]), "r"(a[3]), "r"(b[0]), "r"(b[1]));
}

__device__ __forceinline__ void split1(float x, __nv_bfloat16& h, __nv_bfloat16& l) {
    h = __float2bfloat16(x);
    l = __float2bfloat16(x - __bfloat162float(h));
}
__device__ __forceinline__ uint32_t pack_bf2(__nv_bfloat16 a, __nv_bfloat16 b) {
    __nv_bfloat162 p; p.x = a; p.y = b;
    return *(uint32_t*)&p;
}

// ------------------------- GEMM: C = alpha * Ahi/lo @ (Bhi/lo)^T (+bias) -------------------------
// A: [M,K] K-major (lda), B: [N,K] K-major (ldb). BIAS_MODE: 0 none, 1 per-col, 2 per-row.
// SPLIT_OUT: write bf16 hi/lo instead of fp32 C. 3-term split MMA: hh + hl + lh.
// CTA tile 256x128, warp tile 64x64 (4 m-warps x 2 n-warps).
template<int BIAS_MODE, bool SPLIT_OUT>
__global__ void __launch_bounds__(NTHREADS, 1)
gemm_hmma(const __nv_bfloat16* __restrict__ Ahi, const __nv_bfloat16* __restrict__ Alo,
          int lda, long long sA,
          const __nv_bfloat16* __restrict__ Bhi, const __nv_bfloat16* __restrict__ Blo,
          int ldb, long long sB,
          float* __restrict__ C, __nv_bfloat16* __restrict__ Chi, __nv_bfloat16* __restrict__ Clo,
          int ldc, long long sC,
          int Kdim, float alpha, const float* __restrict__ bias)
{
    extern __shared__ char smem_raw[];
    const uint32_t su = (smem_u32(smem_raw) + 1023u) & ~1023u;

    const int tid = threadIdx.x, lane = tid & 31, wid = tid >> 5;
    const int warp_m = wid >> 1;         // 0..3
    const int warp_n = wid & 1;          // 0..1
    const int m0 = blockIdx.y * BM, n0 = blockIdx.x * BN;
    const int z = blockIdx.z;

    Ahi += (size_t)z * sA;  Alo += (size_t)z * sA;
    Bhi += (size_t)z * sB;  Blo += (size_t)z * sB;
    if (SPLIT_OUT) { Chi += (size_t)z * sC; Clo += (size_t)z * sC; }
    else           { C   += (size_t)z * sC; }

    float acc[4][8][4];
#pragma unroll
    for (int i = 0; i < 4; i++)
#pragma unroll
        for (int j = 0; j < 8; j++)
#pragma unroll
            for (int r = 0; r < 4; r++) acc[i][j][r] = 0.f;

    auto load_stage = [&](int buf, int kt) {
        const uint32_t base = su + buf * STAGE_BYTES;
        const __nv_bfloat16* gAh = Ahi + (size_t)m0 * lda + kt;
        const __nv_bfloat16* gAl = Alo + (size_t)m0 * lda + kt;
        const __nv_bfloat16* gBh = Bhi + (size_t)n0 * ldb + kt;
        const __nv_bfloat16* gBl = Blo + (size_t)n0 * ldb + kt;
        // A: 256 rows x 128B (hi and lo)
#pragma unroll
        for (int i = 0; i < 8; i++) {
            int u = tid + i * NTHREADS;          // 0..2047
            int r = u >> 3, eb = (u & 7) * 16;   // row 0..255, byte 0..112
            uint32_t so = swz((uint32_t)(r * 128 + eb));
            cp16(base +         so, gAh + (size_t)r * lda + (eb >> 1));
            cp16(base + 32768 + so, gAl + (size_t)r * lda + (eb >> 1));
        }
        // B: 128 rows x 128B (hi and lo)
#pragma unroll
        for (int i = 0; i < 4; i++) {
            int u = tid + i * NTHREADS;          // 0..1023
            int r = u >> 3, eb = (u & 7) * 16;   // row 0..127
            uint32_t so = swz((uint32_t)(r * 128 + eb));
            cp16(base + 65536 + so, gBh + (size_t)r * ldb + (eb >> 1));
            cp16(base + 81920 + so, gBl + (size_t)r * ldb + (eb >> 1));
        }
        cp_commit();
    };

    // ldmatrix lane address components
    const int arow = warp_m * 64 + (lane & 7) + ((lane >> 3) & 1) * 8;   // + mi*16
    const int achk = (lane >> 4) * 16;                                    // k byte
    const int brow = warp_n * 64 + (lane & 7) + ((lane >> 4) & 1) * 8;   // + nj2*16
    const int bchk = ((lane >> 3) & 1) * 16;

    auto compute = [&](int buf) {
        const uint32_t aAh = su + buf * STAGE_BYTES;
        const uint32_t aAl = aAh + 32768;
        const uint32_t aBh = aAh + 65536;
        const uint32_t aBl = aAh + 81920;
#pragma unroll
        for (int k16 = 0; k16 < 4; k16++) {
            const uint32_t kbA = (uint32_t)(k16 * 32 + achk);
            const uint32_t kbB = (uint32_t)(k16 * 32 + bchk);
            uint32_t ah[4][4], al[4][4];
#pragma unroll
            for (int mi = 0; mi < 4; mi++) {
                uint32_t off = swz((uint32_t)((arow + mi * 16) * 128) + kbA);
                ldsm4(ah[mi], aAh + off);
                ldsm4(al[mi], aAl + off);
            }
            uint32_t bh[8][2], bl[8][2];
#pragma unroll
            for (int nj2 = 0; nj2 < 4; nj2++) {
                uint32_t off = swz((uint32_t)((brow + nj2 * 16) * 128) + kbB);
                uint32_t t[4];
                ldsm4(t, aBh + off);
                bh[nj2*2][0] = t[0]; bh[nj2*2][1] = t[1];
                bh[nj2*2+1][0] = t[2]; bh[nj2*2+1][1] = t[3];
                ldsm4(t, aBl + off);
                bl[nj2*2][0] = t[0]; bl[nj2*2][1] = t[1];
                bl[nj2*2+1][0] = t[2]; bl[nj2*2+1][1] = t[3];
            }
            // term-major: 32 independent accumulators between same-acc reuses
#pragma unroll
            for (int mi = 0; mi < 4; mi++)
#pragma unroll
                for (int nj = 0; nj < 8; nj++)
                    mma16816(acc[mi][nj], ah[mi], bh[nj]);
#pragma unroll
            for (int mi = 0; mi < 4; mi++)
#pragma unroll
                for (int nj = 0; nj < 8; nj++)
                    mma16816(acc[mi][nj], ah[mi], bl[nj]);
#pragma unroll
            for (int mi = 0; mi < 4; mi++)
#pragma unroll
                for (int nj = 0; nj < 8; nj++)
                    mma16816(acc[mi][nj], al[mi], bh[nj]);
        }
    };

    const int NT = Kdim / BKE;
    load_stage(0, 0);
    for (int t = 0; t < NT; t++) {
        if (t + 1 < NT) { load_stage((t + 1) & 1, (t + 1) * BKE); cp_wait1(); }
        else            { cp_wait0(); }
        __syncthreads();
        compute(t & 1);
        __syncthreads();
    }

    // ---------------- epilogue: registers -> global ----------------
    const int gl = lane >> 2, q = lane & 3;
#pragma unroll
    for (int mi = 0; mi < 4; mi++) {
#pragma unroll
        for (int nj = 0; nj < 8; nj++) {
            const int n = n0 + warp_n * 64 + nj * 8 + q * 2;
            float bcol0 = 0.f, bcol1 = 0.f;
            if (BIAS_MODE == 1) { bcol0 = bias[n]; bcol1 = bias[n + 1]; }
#pragma unroll
            for (int h = 0; h < 2; h++) {
                const int m = m0 + warp_m * 64 + mi * 16 + gl + h * 8;
                float v0 = acc[mi][nj][2 * h + 0] * alpha;
                float v1 = acc[mi][nj][2 * h + 1] * alpha;
                if (BIAS_MODE == 1) { v0 += bcol0; v1 += bcol1; }
                if (BIAS_MODE == 2) { float bb = bias[m]; v0 += bb; v1 += bb; }
                const size_t gidx = (size_t)m * ldc + n;
                if (SPLIT_OUT) {
                    __nv_bfloat16 h0, h1, l0, l1;
                    split1(v0, h0, l0); split1(v1, h1, l1);
                    *(uint32_t*)(Chi + gidx) = pack_bf2(h0, h1);
                    *(uint32_t*)(Clo + gidx) = pack_bf2(l0, l1);
                } else {
                    *(float2*)(C + gidx) = make_float2(v0, v1);
                }
            }
        }
    }
}

// ------------------------- split fp32 -> bf16 hi/lo -------------------------
__global__ void __launch_bounds__(256)
split_f32(const float* __restrict__ x, __nv_bfloat16* __restrict__ hi,
          __nv_bfloat16* __restrict__ lo, int n4)
{
    int i = blockIdx.x * blockDim.x + threadIdx.x;
    if (i >= n4) return;
    float4 t = ((const float4*)x)[i];
    __nv_bfloat16 h0, h1, h2, h3, l0, l1, l2, l3;
    split1(t.x, h0, l0); split1(t.y, h1, l1);
    split1(t.z, h2, l2); split1(t.w, h3, l3);
    uint2 hv, lv;
    hv.x = pack_bf2(h0, h1); hv.y = pack_bf2(h2, h3);
    lv.x = pack_bf2(l0, l1); lv.y = pack_bf2(l2, l3);
    ((uint2*)hi)[i] = hv;
    ((uint2*)lo)[i] = lv;
}

// ------------------------- softmax + intensity, fused bf16 split out -------------------------
__global__ void __launch_bounds__(256)
softmax_split(const float* __restrict__ S, const float* __restrict__ inten,
              __nv_bfloat16* __restrict__ Phi, __nv_bfloat16* __restrict__ Plo)
{
    const size_t row = blockIdx.x;
    const float* sr = S + row * SEQ;
    const float* ir = inten + row * SEQ;
    const int tid = threadIdx.x;

    float v[8];
    float mx = -3.4e38f;
#pragma unroll
    for (int i = 0; i < 8; i++) {
        v[i] = sr[tid + i * 256];
        mx = fmaxf(mx, v[i]);
    }
    __shared__ float red[8];
#pragma unroll
    for (int o = 16; o > 0; o >>= 1)
        mx = fmaxf(mx, __shfl_xor_sync(0xffffffffu, mx, o));
    if ((tid & 31) == 0) red[tid >> 5] = mx;
    __syncthreads();
    mx = red[0];
#pragma unroll
    for (int i = 1; i < 8; i++) mx = fmaxf(mx, red[i]);
    __syncthreads();

    float sum = 0.f;
#pragma unroll
    for (int i = 0; i < 8; i++) {
        v[i] = expf(v[i] - mx);
        sum += v[i];
    }
#pragma unroll
    for (int o = 16; o > 0; o >>= 1)
        sum += __shfl_xor_sync(0xffffffffu, sum, o);
    if ((tid & 31) == 0) red[tid >> 5] = sum;
    __syncthreads();
    sum = 0.f;
#pragma unroll
    for (int i = 0; i < 8; i++) sum += red[i];
    const float inv = 1.f / sum;

    const size_t base = row * SEQ;
#pragma unroll
    for (int i = 0; i < 8; i++) {
        const int idx = tid + i * 256;
        float r = v[i] * inv + ir[idx];
        __nv_bfloat16 h, l;
        split1(r, h, l);
        Phi[base + idx] = h;
        Plo[base + idx] = l;
    }
}

// ------------------------- launch -------------------------
extern "C" void kernel_launch(void* const* d_in, const int* in_sizes, int n_in,
                              void* d_out, int out_size)
{
    const float* X  = (const float*)d_in[0];
    const float* I  = (const float*)d_in[1];
    const float* Wq = (const float*)d_in[2];
    const float* bq = (const float*)d_in[3];
    const float* Wk = (const float*)d_in[4];
    const float* bk = (const float*)d_in[5];
    const float* Wv = (const float*)d_in[6];
    const float* bv = (const float*)d_in[7];
    const float* Wo = (const float*)d_in[8];
    const float* bo = (const float*)d_in[9];
    float* out = (float*)d_out;

    __nv_bfloat16 *Xhi, *Xlo, *Whi, *Wlo, *Qhi, *Qlo, *Khi, *Klo;
    __nv_bfloat16 *Vthi, *Vtlo, *Ohi, *Olo, *Phi, *Plo;
    float* Sc;
    cudaGetSymbolAddress((void**)&Xhi,  g_Xhi);
    cudaGetSymbolAddress((void**)&Xlo,  g_Xlo);
    cudaGetSymbolAddress((void**)&Whi,  g_Whi);
    cudaGetSymbolAddress((void**)&Wlo,  g_Wlo);
    cudaGetSymbolAddress((void**)&Qhi,  g_Qhi);
    cudaGetSymbolAddress((void**)&Qlo,  g_Qlo);
    cudaGetSymbolAddress((void**)&Khi,  g_Khi);
    cudaGetSymbolAddress((void**)&Klo,  g_Klo);
    cudaGetSymbolAddress((void**)&Vthi, g_Vthi);
    cudaGetSymbolAddress((void**)&Vtlo, g_Vtlo);
    cudaGetSymbolAddress((void**)&Ohi,  g_Ohi);
    cudaGetSymbolAddress((void**)&Olo,  g_Olo);
    cudaGetSymbolAddress((void**)&Phi,  g_Phi);
    cudaGetSymbolAddress((void**)&Plo,  g_Plo);
    cudaGetSymbolAddress((void**)&Sc,   g_S);

    cudaFuncSetAttribute(gemm_hmma<1, true>,  cudaFuncAttributeMaxDynamicSharedMemorySize, SMEM_TOTAL);
    cudaFuncSetAttribute(gemm_hmma<2, true>,  cudaFuncAttributeMaxDynamicSharedMemorySize, SMEM_TOTAL);
    cudaFuncSetAttribute(gemm_hmma<0, false>, cudaFuncAttributeMaxDynamicSharedMemorySize, SMEM_TOTAL);
    cudaFuncSetAttribute(gemm_hmma<0, true>,  cudaFuncAttributeMaxDynamicSharedMemorySize, SMEM_TOTAL);
    cudaFuncSetAttribute(gemm_hmma<1, false>, cudaFuncAttributeMaxDynamicSharedMemorySize, SMEM_TOTAL);

    const int WSZ = DMODEL * DMODEL;

    // split inputs to bf16 hi/lo
    split_f32<<<(BS_ROWS * DMODEL / 4 + 255) / 256, 256>>>(X, Xhi, Xlo, BS_ROWS * DMODEL / 4);
    split_f32<<<(WSZ / 4 + 255) / 256, 256>>>(Wq, Whi + 0 * WSZ, Wlo + 0 * WSZ, WSZ / 4);
    split_f32<<<(WSZ / 4 + 255) / 256, 256>>>(Wk, Whi + 1 * WSZ, Wlo + 1 * WSZ, WSZ / 4);
    split_f32<<<(WSZ / 4 + 255) / 256, 256>>>(Wv, Whi + 2 * WSZ, Wlo + 2 * WSZ, WSZ / 4);
    split_f32<<<(WSZ / 4 + 255) / 256, 256>>>(Wo, Whi + 3 * WSZ, Wlo + 3 * WSZ, WSZ / 4);

    dim3 blk(NTHREADS);

    // Q = X @ Wq^T + bq   -> split
    dim3 gP(DMODEL / BN, BS_ROWS / BM, 1);  // (8, 32)
    gemm_hmma<1, true><<<gP, blk, SMEM_TOTAL>>>(
        Xhi, Xlo, DMODEL, 0, Whi + 0 * WSZ, Wlo + 0 * WSZ, DMODEL, 0,
        nullptr, Qhi, Qlo, DMODEL, 0, DMODEL, 1.f, bq);
    // K = X @ Wk^T + bk   -> split
    gemm_hmma<1, true><<<gP, blk, SMEM_TOTAL>>>(
        Xhi, Xlo, DMODEL, 0, Whi + 1 * WSZ, Wlo + 1 * WSZ, DMODEL, 0,
        nullptr, Khi, Klo, DMODEL, 0, DMODEL, 1.f, bk);
    // V^T = Wv @ X^T + bv(row)  -> split, Vt[d, b*S+s], ld = 8192
    dim3 gV(BS_ROWS / BN, DMODEL / BM, 1);  // (64, 4)
    gemm_hmma<2, true><<<gV, blk, SMEM_TOTAL>>>(
        Whi + 2 * WSZ, Wlo + 2 * WSZ, DMODEL, 0, Xhi, Xlo, DMODEL, 0,
        nullptr, Vthi, Vtlo, BS_ROWS, 0, DMODEL, 1.f, bv);
    // scores = (Q K^T)/32  -> fp32, batched
    dim3 gS(SEQ / BN, SEQ / BM, BATCH);     // (16, 8, 4)
    gemm_hmma<0, false><<<gS, blk, SMEM_TOTAL>>>(
        Qhi, Qlo, DMODEL, (long long)SEQ * DMODEL,
        Khi, Klo, DMODEL, (long long)SEQ * DMODEL,
        Sc, nullptr, nullptr, SEQ, (long long)SEQ * SEQ,
        DMODEL, 0.03125f, nullptr);
    // attn = softmax(scores) + intensity -> split
    softmax_split<<<BATCH * SEQ, 256>>>(Sc, I, Phi, Plo);
    // O = attn @ (Vt)^T  -> split, batched (B slice = column offset b*S within Vt rows)
    dim3 gO(DMODEL / BN, SEQ / BM, BATCH);  // (8, 8, 4)
    gemm_hmma<0, true><<<gO, blk, SMEM_TOTAL>>>(
        Phi, Plo, SEQ, (long long)SEQ * SEQ,
        Vthi, Vtlo, BS_ROWS, (long long)SEQ,
        nullptr, Ohi, Olo, DMODEL, (long long)SEQ * DMODEL,
        SEQ, 1.f, nullptr);
    // out = O @ Wo^T + bo  -> fp32
    gemm_hmma<1, false><<<gP, blk, SMEM_TOTAL>>>(
        Ohi, Olo, DMODEL, 0, Whi + 3 * WSZ, Wlo + 3 * WSZ, DMODEL, 0,
        out, nullptr, nullptr, DMODEL, 0, DMODEL, 1.f, bo);
}